// round 8
// baseline (speedup 1.0000x reference)
#include <cuda_runtime.h>
#include <cuda_fp16.h>

#define DD 64
#define HH 256
#define MAXG 4096
#define BN_EPS 1e-3f
#define NT 64            // nodes per tile (GEMM M)
#define AST 136          // A smem row stride in halves (128 + 8 pad -> 272B)
#define ABUF 17408       // bytes per A buffer

__device__ float g_pooled[MAXG * DD];

// ---------- shared memory byte map (dynamic) ----------
#define SM_A    0            // A bufs: 4 x 17408 = 69632
#define SM_RR   69632        // RR staging: 64 x 68 fp32 = 17408 B
#define SM_BI   87040        // b_i (64 f)
#define SM_BJ   87296        // b_j (64 f)
#define SM_SEG  87552        // 4 x 64 ints = 1024
#define SM_TOTAL 88576

__device__ __forceinline__ float tanh_fast(float v) {
    float r;
    asm("tanh.approx.f32 %0, %1;" : "=f"(r) : "f"(v));
    return r;
}
// sigmoid(t) for t in [-1,1]: odd Taylor poly, |err| < 3e-5 (no second MUFU)
__device__ __forceinline__ float sigmoid_unit(float t) {
    const float t2 = t * t;
    float p = fmaf(t2, -2.108134920634921e-4f, 2.0833333333e-3f);
    p = fmaf(t2, p, -2.0833333333e-2f);
    p = fmaf(t2, p, 0.25f);
    return fmaf(t, p, 0.5f);
}
__device__ __forceinline__ unsigned int smem_u32(const void* p) {
    unsigned int a;
    asm("{ .reg .u64 t; cvta.to.shared.u64 t, %1; cvt.u32.u64 %0, t; }" : "=r"(a) : "l"(p));
    return a;
}

__global__ void zero_pooled_kernel(int n) {
    for (int i = blockIdx.x * blockDim.x + threadIdx.x; i < n; i += gridDim.x * blockDim.x)
        g_pooled[i] = 0.0f;
}

extern __shared__ char smc[];

__global__ __launch_bounds__(256, 2) void node_mma_kernel(
    const float* __restrict__ x, const float* __restrict__ h,
    const float* __restrict__ W_i, const float* __restrict__ b_i,
    const float* __restrict__ W_j, const float* __restrict__ b_j,
    const int* __restrict__ seg, int N, int ntiles)
{
    const int tid  = threadIdx.x;
    const int w    = tid >> 5, lane = tid & 31;   // warp w owns interleaved cols [16w,16w+16)
    const int lr   = lane >> 2;       // groupID 0..7
    const int lc   = lane & 3;        // 0..3

    float* srr = (float*)(smc + SM_RR);
    float* sbi = (float*)(smc + SM_BI);
    float* sbj = (float*)(smc + SM_BJ);
    int*  sseg = (int*)(smc + SM_SEG);   // [4][64], slot = (it index) & 3

    if (tid < 64) {
        sbi[tid] = b_i[tid];
        sbj[tid] = b_j[tid];
    }

    // ---- Weight-stationary B fragments (fp16), col-owned per warp (no dup) ----
    unsigned int Bf[2][8][2];
#pragma unroll
    for (int nf = 0; nf < 2; nf++) {
        const int n = w * 16 + nf * 8 + lr;
        const int pcol = n >> 1;
        const bool isP = (n & 1) == 0;
#pragma unroll
        for (int ks = 0; ks < 8; ks++) {
#pragma unroll
            for (int i = 0; i < 2; i++) {
                const int k0 = ks * 16 + lc * 2 + i * 8;
                float v0, v1;
                if (isP) {
                    v0 = W_i[k0 * 64 + pcol];
                    v1 = W_i[(k0 + 1) * 64 + pcol];
                } else if (k0 < 64) {
                    v0 = W_j[k0 * 64 + pcol];
                    v1 = W_j[(k0 + 1) * 64 + pcol];
                } else {
                    v0 = 0.0f; v1 = 0.0f;
                }
                __half2 hv = __floats2half2_rn(v0, v1);
                Bf[nf][ks][i] = *(unsigned int*)&hv;
            }
        }
    }

    // ---- register-staged tile loaders (it = tile index / gridDim.x) ----
    uint2 stc[8];
    auto ldg_tile = [&](int it) {
        const int tile = blockIdx.x + it * (int)gridDim.x;
        const int base = tile * NT;
#pragma unroll
        for (int j = 0; j < 8; j++) {
            const int idx = tid + j * 256;          // 2048 float4 slots
            const int n = idx >> 5, kc = (idx & 31) << 2;
            const int gn = base + n;
            float4 v = make_float4(0.f, 0.f, 0.f, 0.f);
            if (tile < ntiles && gn < N) {
                const float* src = (kc < 64) ? (h + (size_t)gn * 64 + kc)
                                             : (x + (size_t)gn * 64 + (kc - 64));
                v = *(const float4*)src;
            }
            __half2 lo = __floats2half2_rn(v.x, v.y);
            __half2 hi = __floats2half2_rn(v.z, v.w);
            stc[j].x = *(unsigned int*)&lo;
            stc[j].y = *(unsigned int*)&hi;
        }
    };
    auto sts_tile = [&](int it) {
        char* ab = smc + SM_A + (it & 3) * ABUF;
#pragma unroll
        for (int j = 0; j < 8; j++) {
            const int idx = tid + j * 256;
            const int n = idx >> 5, kc = (idx & 31) << 2;
            *(uint2*)(ab + (n * AST + kc) * 2) = stc[j];
        }
    };
    auto stage_seg = [&](int it) {
        if (tid < NT) {
            const int tile = blockIdx.x + it * (int)gridDim.x;
            const int gn = tile * NT + tid;
            sseg[(it & 3) * 64 + tid] = (gn < N && tile < ntiles) ? seg[gn] : -1;
        }
    };

    const int lrow = lane & 15;                // ldmatrix row within 16
    const int lcol8 = (lane >> 4) << 3;        // ldmatrix col-half offset

    // ---- one tile: GEMM + epilogue + warp-local reduce (no CTA barrier) ----
    auto process_tile = [&](int it) {
        const int tile = blockIdx.x + it * (int)gridDim.x;
        if (tile >= ntiles) return;
        const char* sA = smc + SM_A + (it & 3) * ABUF;
        const int* mseg = sseg + (it & 3) * 64;

        float C[4][2][4];
#pragma unroll
        for (int mf = 0; mf < 4; mf++)
#pragma unroll
            for (int nf = 0; nf < 2; nf++)
#pragma unroll
                for (int q = 0; q < 4; q++) C[mf][nf][q] = 0.0f;

#pragma unroll
        for (int ks = 0; ks < 8; ks++) {
#pragma unroll
            for (int mf = 0; mf < 4; mf++) {
                unsigned int a[4];
                const unsigned int addr = smem_u32(
                    sA + ((mf * 16 + lrow) * AST + ks * 16 + lcol8) * 2);
                asm volatile(
                    "ldmatrix.sync.aligned.m8n8.x4.shared.b16 {%0,%1,%2,%3}, [%4];"
                    : "=r"(a[0]), "=r"(a[1]), "=r"(a[2]), "=r"(a[3])
                    : "r"(addr));
#pragma unroll
                for (int nf = 0; nf < 2; nf++)
                    asm volatile(
                        "mma.sync.aligned.m16n8k16.row.col.f32.f16.f16.f32 "
                        "{%0,%1,%2,%3}, {%4,%5,%6,%7}, {%8,%9}, {%0,%1,%2,%3};"
                        : "+f"(C[mf][nf][0]), "+f"(C[mf][nf][1]),
                          "+f"(C[mf][nf][2]), "+f"(C[mf][nf][3])
                        : "r"(a[0]), "r"(a[1]), "r"(a[2]), "r"(a[3]),
                          "r"(Bf[nf][ks][0]), "r"(Bf[nf][ks][1]));
            }
        }

        // Epilogue -> warp-local srr columns
#pragma unroll
        for (int nf = 0; nf < 2; nf++) {
            const int pcol = w * 8 + nf * 4 + lc;
            const float bi = sbi[pcol], bj = sbj[pcol];
#pragma unroll
            for (int mf = 0; mf < 4; mf++) {
                const int r0 = mf * 16 + lr;
#pragma unroll
                for (int rp = 0; rp < 2; rp++) {
                    const float P = C[mf][nf][rp * 2] + bi;
                    const float J = C[mf][nf][rp * 2 + 1] + bj;
                    srr[(r0 + rp * 8) * 68 + pcol] =
                        sigmoid_unit(tanh_fast(P)) * fmaxf(J, 0.0f);
                }
            }
        }
        __syncwarp();

        // Warp-local reduce: lane -> (col = w*8 + (lane&7), 16-node strip)
        const int c = w * 8 + (lane & 7);
        const int n0 = (lane >> 3) * 16;
        float acc = 0.0f;
        int cur = mseg[n0];
#pragma unroll 4
        for (int n = n0; n < n0 + 16; n++) {
            const int s = mseg[n];
            if (s != cur) {
                if (cur >= 0) atomicAdd(&g_pooled[cur * DD + c], acc);
                acc = 0.0f;
                cur = s;
            }
            acc += srr[n * 68 + c];
        }
        if (cur >= 0) atomicAdd(&g_pooled[cur * DD + c], acc);
        __syncwarp();   // srr reads done before this warp's next epilogue writes
    };

    // ---- Prologue: stage it=0,1; prefetch it=2 into regs ----
    ldg_tile(0);
    sts_tile(0);
    ldg_tile(1);
    sts_tile(1);
    stage_seg(0);
    stage_seg(1);
    ldg_tile(2);
    __syncthreads();   // bufs 0,1 + segs 0,1 + biases visible

    // ---- Pair loop: ONE CTA barrier per 2 tiles ----
    for (int it = 0; blockIdx.x + it * (int)gridDim.x < ntiles; it += 2) {
        process_tile(it);
        sts_tile(it + 2);        // stc holds it+2 (prefetched last pair / prologue)
        stage_seg(it + 2);
        ldg_tile(it + 3);        // prefetch it+3 into regs (hides DRAM latency)
        process_tile(it + 1);
        sts_tile(it + 3);
        stage_seg(it + 3);
        ldg_tile(it + 4);        // prefetch it+4 for next pair
        __syncthreads();         // bufs/segs (it+2, it+3) visible; old bufs reusable
    }
}

// Per-graph readout: BN(inference) -> Dense(64->256)+ReLU -> Dense(256->1)
__global__ void readout_kernel(
    const float* __restrict__ gamma, const float* __restrict__ beta,
    const float* __restrict__ mov_mean, const float* __restrict__ mov_var,
    const float* __restrict__ W_h1, const float* __restrict__ b_h1,
    const float* __restrict__ W_out, const float* __restrict__ b_out,
    float* __restrict__ out)
{
    __shared__ float bn[DD];
    __shared__ float warp_part[8];
    const int g = blockIdx.x;
    const int t = threadIdx.x;

    if (t < DD) {
        const float p = g_pooled[g * DD + t];
        bn[t] = (p - mov_mean[t]) * rsqrtf(mov_var[t] + BN_EPS) * gamma[t] + beta[t];
    }
    __syncthreads();

    float y = 0.0f;
#pragma unroll 8
    for (int d = 0; d < DD; d++)
        y = fmaf(bn[d], W_h1[d * HH + t], y);
    y = fmaxf(y + b_h1[t], 0.0f);

    float v = y * W_out[t];
#pragma unroll
    for (int o = 16; o > 0; o >>= 1) v += __shfl_xor_sync(0xffffffffu, v, o);
    if ((t & 31) == 0) warp_part[t >> 5] = v;
    __syncthreads();
    if (t < 32) {
        float s = (t < 8) ? warp_part[t] : 0.0f;
#pragma unroll
        for (int o = 4; o > 0; o >>= 1) s += __shfl_xor_sync(0xffffffffu, s, o);
        if (t == 0) out[g] = s + b_out[0];
    }
}

extern "C" void kernel_launch(void* const* d_in, const int* in_sizes, int n_in,
                              void* d_out, int out_size)
{
    const float* x        = (const float*)d_in[0];
    const float* h        = (const float*)d_in[1];
    const float* W_i      = (const float*)d_in[2];
    const float* b_i      = (const float*)d_in[3];
    const float* W_j      = (const float*)d_in[4];
    const float* b_j      = (const float*)d_in[5];
    const float* gamma    = (const float*)d_in[6];
    const float* beta     = (const float*)d_in[7];
    const float* mov_mean = (const float*)d_in[8];
    const float* mov_var  = (const float*)d_in[9];
    const float* W_h1     = (const float*)d_in[10];
    const float* b_h1     = (const float*)d_in[11];
    const float* W_out    = (const float*)d_in[12];
    const float* b_out    = (const float*)d_in[13];
    const int*   seg      = (const int*)d_in[14];

    const int N = in_sizes[14];
    const int G = out_size;
    const int ntiles = (N + NT - 1) / NT;

    zero_pooled_kernel<<<256, 256>>>(G * DD);

    cudaFuncSetAttribute(node_mma_kernel, cudaFuncAttributeMaxDynamicSharedMemorySize,
                         SM_TOTAL);
    int grid = 296;
    if (grid > ntiles) grid = ntiles;
    node_mma_kernel<<<grid, 256, SM_TOTAL>>>(x, h, W_i, b_i, W_j, b_j, seg, N, ntiles);

    readout_kernel<<<G, 256>>>(gamma, beta, mov_mean, mov_var, W_h1, b_h1, W_out, b_out,
                               (float*)d_out);
}

// round 9
// speedup vs baseline: 1.7909x; 1.7909x over previous
#include <cuda_runtime.h>
#include <cuda_fp16.h>

#define DD 64
#define HH 256
#define MAXG 4096
#define BN_EPS 1e-3f
#define NT 64            // nodes per tile (GEMM M)
#define AST 136          // A smem row stride in halves (128 + 8 pad -> 272B)

__device__ float g_pooled[MAXG * DD];

// ---------- shared memory byte map (dynamic) ----------
#define SM_A0   0            // A buf 0: 64 x 136 fp16 = 17408 B
#define SM_A1   17408        // A buf 1
#define SM_RR   34816        // RR staging: 64 x 68 fp32 = 17408 B
#define SM_BI   52224        // b_i (64 f)
#define SM_BJ   52480        // b_j (64 f)
#define SM_SEG  52736        // 2 x 64 ints (double-buffered)
#define SM_TOTAL 53248

__device__ __forceinline__ float tanh_fast(float v) {
    float r;
    asm("tanh.approx.f32 %0, %1;" : "=f"(r) : "f"(v));
    return r;
}
// sigmoid(t) for t in [-1,1]: odd Taylor poly, |err| < 3e-5 (no second MUFU)
__device__ __forceinline__ float sigmoid_unit(float t) {
    const float t2 = t * t;
    float p = fmaf(t2, -2.108134920634921e-4f, 2.0833333333e-3f);
    p = fmaf(t2, p, -2.0833333333e-2f);
    p = fmaf(t2, p, 0.25f);
    return fmaf(t, p, 0.5f);
}
__device__ __forceinline__ unsigned int smem_u32(const void* p) {
    unsigned int a;
    asm("{ .reg .u64 t; cvta.to.shared.u64 t, %1; cvt.u32.u64 %0, t; }" : "=r"(a) : "l"(p));
    return a;
}

__global__ void zero_pooled_kernel(int n) {
    for (int i = blockIdx.x * blockDim.x + threadIdx.x; i < n; i += gridDim.x * blockDim.x)
        g_pooled[i] = 0.0f;
}

extern __shared__ char smc[];

__global__ __launch_bounds__(256, 2) void node_mma_kernel(
    const float* __restrict__ x, const float* __restrict__ h,
    const float* __restrict__ W_i, const float* __restrict__ b_i,
    const float* __restrict__ W_j, const float* __restrict__ b_j,
    const int* __restrict__ seg, int N, int ntiles)
{
    const int tid  = threadIdx.x;
    const int w    = tid >> 5, lane = tid & 31;   // warp w owns interleaved cols [16w,16w+16)
    const int lr   = lane >> 2;       // groupID 0..7
    const int lc   = lane & 3;        // 0..3

    float* srr = (float*)(smc + SM_RR);
    float* sbi = (float*)(smc + SM_BI);
    float* sbj = (float*)(smc + SM_BJ);
    int*  sseg = (int*)(smc + SM_SEG);   // [2][64]

    if (tid < 64) {
        sbi[tid] = b_i[tid];
        sbj[tid] = b_j[tid];
    }

    // ---- Weight-stationary B fragments (fp16), col-owned per warp (no dup) ----
    unsigned int Bf[2][8][2];
#pragma unroll
    for (int nf = 0; nf < 2; nf++) {
        const int n = w * 16 + nf * 8 + lr;
        const int pcol = n >> 1;
        const bool isP = (n & 1) == 0;
#pragma unroll
        for (int ks = 0; ks < 8; ks++) {
#pragma unroll
            for (int i = 0; i < 2; i++) {
                const int k0 = ks * 16 + lc * 2 + i * 8;
                float v0, v1;
                if (isP) {
                    v0 = W_i[k0 * 64 + pcol];
                    v1 = W_i[(k0 + 1) * 64 + pcol];
                } else if (k0 < 64) {
                    v0 = W_j[k0 * 64 + pcol];
                    v1 = W_j[(k0 + 1) * 64 + pcol];
                } else {
                    v0 = 0.0f; v1 = 0.0f;
                }
                __half2 hv = __floats2half2_rn(v0, v1);
                Bf[nf][ks][i] = *(unsigned int*)&hv;
            }
        }
    }

    // ---- register-staged tile loaders (convert to half2 at load time) ----
    uint2 stc[8];
    auto ldg_tile = [&](int tile) {
        const int base = tile * NT;
#pragma unroll
        for (int j = 0; j < 8; j++) {
            const int idx = tid + j * 256;          // 2048 float4 slots
            const int n = idx >> 5, kc = (idx & 31) << 2;
            const int gn = base + n;
            float4 v = make_float4(0.f, 0.f, 0.f, 0.f);
            if (tile < ntiles && gn < N) {
                const float* src = (kc < 64) ? (h + (size_t)gn * 64 + kc)
                                             : (x + (size_t)gn * 64 + (kc - 64));
                v = *(const float4*)src;
            }
            __half2 lo = __floats2half2_rn(v.x, v.y);
            __half2 hi = __floats2half2_rn(v.z, v.w);
            stc[j].x = *(unsigned int*)&lo;
            stc[j].y = *(unsigned int*)&hi;
        }
    };
    auto sts_tile = [&](int buf) {
        char* ab = smc + (buf ? SM_A1 : SM_A0);
#pragma unroll
        for (int j = 0; j < 8; j++) {
            const int idx = tid + j * 256;
            const int n = idx >> 5, kc = (idx & 31) << 2;
            *(uint2*)(ab + (n * AST + kc) * 2) = stc[j];
        }
    };
    auto stage_seg = [&](int tile, int buf) {
        if (tid < NT) {
            const int gn = tile * NT + tid;
            sseg[buf * 64 + tid] = (gn < N && tile < ntiles) ? seg[gn] : -1;
        }
    };

    // Prologue: tile0 -> buf0 (+seg); tile1 -> regs
    ldg_tile(blockIdx.x);
    sts_tile(0);
    stage_seg(blockIdx.x, 0);
    ldg_tile(blockIdx.x + gridDim.x);
    __syncthreads();   // covers sbi/sbj + buf0 + seg0

    const int lrow = lane & 15;                // ldmatrix row within 16
    const int lcol8 = (lane >> 4) << 3;        // ldmatrix col-half offset

    for (int it = 0;; it++) {
        const int tile = blockIdx.x + it * gridDim.x;
        if (tile >= ntiles) break;
        const int buf = it & 1;
        const char* sA = smc + (buf ? SM_A1 : SM_A0);
        const int* mseg = sseg + buf * 64;

        // ---- GEMM: all 64 rows x this warp's 16 interleaved cols ----
        float C[4][2][4];
#pragma unroll
        for (int mf = 0; mf < 4; mf++)
#pragma unroll
            for (int nf = 0; nf < 2; nf++)
#pragma unroll
                for (int q = 0; q < 4; q++) C[mf][nf][q] = 0.0f;

#pragma unroll
        for (int ks = 0; ks < 8; ks++) {
#pragma unroll
            for (int mf = 0; mf < 4; mf++) {
                unsigned int a[4];
                const unsigned int addr = smem_u32(
                    sA + ((mf * 16 + lrow) * AST + ks * 16 + lcol8) * 2);
                asm volatile(
                    "ldmatrix.sync.aligned.m8n8.x4.shared.b16 {%0,%1,%2,%3}, [%4];"
                    : "=r"(a[0]), "=r"(a[1]), "=r"(a[2]), "=r"(a[3])
                    : "r"(addr));
#pragma unroll
                for (int nf = 0; nf < 2; nf++)
                    asm volatile(
                        "mma.sync.aligned.m16n8k16.row.col.f32.f16.f16.f32 "
                        "{%0,%1,%2,%3}, {%4,%5,%6,%7}, {%8,%9}, {%0,%1,%2,%3};"
                        : "+f"(C[mf][nf][0]), "+f"(C[mf][nf][1]),
                          "+f"(C[mf][nf][2]), "+f"(C[mf][nf][3])
                        : "r"(a[0]), "r"(a[1]), "r"(a[2]), "r"(a[3]),
                          "r"(Bf[nf][ks][0]), "r"(Bf[nf][ks][1]));
            }
        }

        // STS tile it+1 into the other buffer (consumed in it-1; sync'd)
        sts_tile(buf ^ 1);
        // Prefetch tile it+2 into regs (DRAM latency hides under epilogue)
        ldg_tile(blockIdx.x + (it + 2) * gridDim.x);

        // ---- Epilogue -> warp-local srr columns [8w, 8w+8) ----
#pragma unroll
        for (int nf = 0; nf < 2; nf++) {
            const int pcol = w * 8 + nf * 4 + lc;
            const float bi = sbi[pcol], bj = sbj[pcol];
#pragma unroll
            for (int mf = 0; mf < 4; mf++) {
                const int r0 = mf * 16 + lr;
#pragma unroll
                for (int rp = 0; rp < 2; rp++) {
                    const float P = C[mf][nf][rp * 2] + bi;
                    const float J = C[mf][nf][rp * 2 + 1] + bj;
                    srr[(r0 + rp * 8) * 68 + pcol] =
                        sigmoid_unit(tanh_fast(P)) * fmaxf(J, 0.0f);
                }
            }
        }
        __syncwarp();   // warp-local: same warp wrote these columns

        // ---- Warp-local sorted-segment reduce: warp w reduces cols [8w,8w+8) ----
        // lane -> (col = w*8 + (lane&7), node strip [(lane>>3)*16, +16))
        {
            const int c = w * 8 + (lane & 7);
            const int n0 = (lane >> 3) * 16;
            float acc = 0.0f;
            int cur = mseg[n0];
#pragma unroll 4
            for (int n = n0; n < n0 + 16; n++) {
                const int s = mseg[n];
                if (s != cur) {
                    if (cur >= 0) atomicAdd(&g_pooled[cur * DD + c], acc);
                    acc = 0.0f;
                    cur = s;
                }
                acc += srr[n * 68 + c];
            }
            if (cur >= 0) atomicAdd(&g_pooled[cur * DD + c], acc);
        }

        // Stage next tile's segment ids into the other sseg buffer
        stage_seg(blockIdx.x + (it + 1) * gridDim.x, buf ^ 1);

        __syncthreads();   // A buf^1 + sseg buf^1 visible; srr free for next tile
    }
}

// Per-graph readout: BN(inference) -> Dense(64->256)+ReLU -> Dense(256->1)
__global__ void readout_kernel(
    const float* __restrict__ gamma, const float* __restrict__ beta,
    const float* __restrict__ mov_mean, const float* __restrict__ mov_var,
    const float* __restrict__ W_h1, const float* __restrict__ b_h1,
    const float* __restrict__ W_out, const float* __restrict__ b_out,
    float* __restrict__ out)
{
    __shared__ float bn[DD];
    __shared__ float warp_part[8];
    const int g = blockIdx.x;
    const int t = threadIdx.x;

    if (t < DD) {
        const float p = g_pooled[g * DD + t];
        bn[t] = (p - mov_mean[t]) * rsqrtf(mov_var[t] + BN_EPS) * gamma[t] + beta[t];
    }
    __syncthreads();

    float y = 0.0f;
#pragma unroll 8
    for (int d = 0; d < DD; d++)
        y = fmaf(bn[d], W_h1[d * HH + t], y);
    y = fmaxf(y + b_h1[t], 0.0f);

    float v = y * W_out[t];
#pragma unroll
    for (int o = 16; o > 0; o >>= 1) v += __shfl_xor_sync(0xffffffffu, v, o);
    if ((t & 31) == 0) warp_part[t >> 5] = v;
    __syncthreads();
    if (t < 32) {
        float s = (t < 8) ? warp_part[t] : 0.0f;
#pragma unroll
        for (int o = 4; o > 0; o >>= 1) s += __shfl_xor_sync(0xffffffffu, s, o);
        if (t == 0) out[g] = s + b_out[0];
    }
}

extern "C" void kernel_launch(void* const* d_in, const int* in_sizes, int n_in,
                              void* d_out, int out_size)
{
    const float* x        = (const float*)d_in[0];
    const float* h        = (const float*)d_in[1];
    const float* W_i      = (const float*)d_in[2];
    const float* b_i      = (const float*)d_in[3];
    const float* W_j      = (const float*)d_in[4];
    const float* b_j      = (const float*)d_in[5];
    const float* gamma    = (const float*)d_in[6];
    const float* beta     = (const float*)d_in[7];
    const float* mov_mean = (const float*)d_in[8];
    const float* mov_var  = (const float*)d_in[9];
    const float* W_h1     = (const float*)d_in[10];
    const float* b_h1     = (const float*)d_in[11];
    const float* W_out    = (const float*)d_in[12];
    const float* b_out    = (const float*)d_in[13];
    const int*   seg      = (const int*)d_in[14];

    const int N = in_sizes[14];
    const int G = out_size;
    const int ntiles = (N + NT - 1) / NT;

    zero_pooled_kernel<<<256, 256>>>(G * DD);

    cudaFuncSetAttribute(node_mma_kernel, cudaFuncAttributeMaxDynamicSharedMemorySize,
                         SM_TOTAL);
    int grid = 296;
    if (grid > ntiles) grid = ntiles;
    node_mma_kernel<<<grid, 256, SM_TOTAL>>>(x, h, W_i, b_i, W_j, b_j, seg, N, ntiles);

    readout_kernel<<<G, 256>>>(gamma, beta, mov_mean, mov_var, W_h1, b_h1, W_out, b_out,
                               (float*)d_out);
}

// round 10
// speedup vs baseline: 2.0576x; 1.1489x over previous
#include <cuda_runtime.h>
#include <cuda_fp16.h>

#define DD 64
#define HH 256
#define MAXG 4096
#define BN_EPS 1e-3f
#define NT 64            // nodes per tile (GEMM M)
#define AST 136          // A smem row stride in halves (128 + 8 pad -> 272B)

__device__ float g_pooled[MAXG * DD];

// ---------- shared memory byte map (dynamic) ----------
#define SM_A0   0            // A buf 0: 64 x 136 fp16 = 17408 B
#define SM_A1   17408        // A buf 1
#define SM_RR   34816        // RR staging TRANSPOSED [col][node]: 64 x 68 fp32 = 17408 B
#define SM_BI   52224        // b_i (64 f)
#define SM_BJ   52480        // b_j (64 f)
#define SM_SEG  52736        // 2 x 64 ints (double-buffered)
#define SM_TOTAL 53248

__device__ __forceinline__ float tanh_fast(float v) {
    float r;
    asm("tanh.approx.f32 %0, %1;" : "=f"(r) : "f"(v));
    return r;
}
// sigmoid(t) for t in [-1,1]: odd Taylor poly, |err| < 3e-5 (no second MUFU)
__device__ __forceinline__ float sigmoid_unit(float t) {
    const float t2 = t * t;
    float p = fmaf(t2, -2.108134920634921e-4f, 2.0833333333e-3f);
    p = fmaf(t2, p, -2.0833333333e-2f);
    p = fmaf(t2, p, 0.25f);
    return fmaf(t, p, 0.5f);
}
__device__ __forceinline__ unsigned int smem_u32(const void* p) {
    unsigned int a;
    asm("{ .reg .u64 t; cvta.to.shared.u64 t, %1; cvt.u32.u64 %0, t; }" : "=r"(a) : "l"(p));
    return a;
}

__global__ void zero_pooled_kernel(int n) {
    for (int i = blockIdx.x * blockDim.x + threadIdx.x; i < n; i += gridDim.x * blockDim.x)
        g_pooled[i] = 0.0f;
}

extern __shared__ char smc[];

__global__ __launch_bounds__(256, 2) void node_mma_kernel(
    const float* __restrict__ x, const float* __restrict__ h,
    const float* __restrict__ W_i, const float* __restrict__ b_i,
    const float* __restrict__ W_j, const float* __restrict__ b_j,
    const int* __restrict__ seg, int N, int ntiles)
{
    const int tid  = threadIdx.x;
    const int w    = tid >> 5, lane = tid & 31;   // warp w owns interleaved cols [16w,16w+16)
    const int lr   = lane >> 2;       // groupID 0..7
    const int lc   = lane & 3;        // 0..3

    float* srr = (float*)(smc + SM_RR);     // [col][node], stride 68
    float* sbi = (float*)(smc + SM_BI);
    float* sbj = (float*)(smc + SM_BJ);
    int*  sseg = (int*)(smc + SM_SEG);   // [2][64]

    if (tid < 64) {
        sbi[tid] = b_i[tid];
        sbj[tid] = b_j[tid];
    }

    // ---- Weight-stationary B fragments (fp16), col-owned per warp (no dup) ----
    unsigned int Bf[2][8][2];
#pragma unroll
    for (int nf = 0; nf < 2; nf++) {
        const int n = w * 16 + nf * 8 + lr;
        const int pcol = n >> 1;
        const bool isP = (n & 1) == 0;
#pragma unroll
        for (int ks = 0; ks < 8; ks++) {
#pragma unroll
            for (int i = 0; i < 2; i++) {
                const int k0 = ks * 16 + lc * 2 + i * 8;
                float v0, v1;
                if (isP) {
                    v0 = W_i[k0 * 64 + pcol];
                    v1 = W_i[(k0 + 1) * 64 + pcol];
                } else if (k0 < 64) {
                    v0 = W_j[k0 * 64 + pcol];
                    v1 = W_j[(k0 + 1) * 64 + pcol];
                } else {
                    v0 = 0.0f; v1 = 0.0f;
                }
                __half2 hv = __floats2half2_rn(v0, v1);
                Bf[nf][ks][i] = *(unsigned int*)&hv;
            }
        }
    }

    // ---- register-staged tile loaders (convert to half2 at load time) ----
    uint2 stc[8];
    auto ldg_tile = [&](int tile) {
        const int base = tile * NT;
#pragma unroll
        for (int j = 0; j < 8; j++) {
            const int idx = tid + j * 256;          // 2048 float4 slots
            const int n = idx >> 5, kc = (idx & 31) << 2;
            const int gn = base + n;
            float4 v = make_float4(0.f, 0.f, 0.f, 0.f);
            if (tile < ntiles && gn < N) {
                const float* src = (kc < 64) ? (h + (size_t)gn * 64 + kc)
                                             : (x + (size_t)gn * 64 + (kc - 64));
                v = *(const float4*)src;
            }
            __half2 lo = __floats2half2_rn(v.x, v.y);
            __half2 hi = __floats2half2_rn(v.z, v.w);
            stc[j].x = *(unsigned int*)&lo;
            stc[j].y = *(unsigned int*)&hi;
        }
    };
    auto sts_tile = [&](int buf) {
        char* ab = smc + (buf ? SM_A1 : SM_A0);
#pragma unroll
        for (int j = 0; j < 8; j++) {
            const int idx = tid + j * 256;
            const int n = idx >> 5, kc = (idx & 31) << 2;
            *(uint2*)(ab + (n * AST + kc) * 2) = stc[j];
        }
    };
    auto stage_seg = [&](int tile, int buf) {
        if (tid < NT) {
            const int gn = tile * NT + tid;
            sseg[buf * 64 + tid] = (gn < N && tile < ntiles) ? seg[gn] : -1;
        }
    };

    // Prologue: tile0 -> buf0 (+seg); tile1 -> regs
    ldg_tile(blockIdx.x);
    sts_tile(0);
    stage_seg(blockIdx.x, 0);
    ldg_tile(blockIdx.x + gridDim.x);
    __syncthreads();   // covers sbi/sbj + buf0 + seg0

    const int lrow = lane & 15;                // ldmatrix row within 16
    const int lcol8 = (lane >> 4) << 3;        // ldmatrix col-half offset

    for (int it = 0;; it++) {
        const int tile = blockIdx.x + it * gridDim.x;
        if (tile >= ntiles) break;
        const int buf = it & 1;
        const char* sA = smc + (buf ? SM_A1 : SM_A0);
        const int* mseg = sseg + buf * 64;

        // ---- GEMM: all 64 rows x this warp's 16 interleaved cols ----
        float C[4][2][4];
#pragma unroll
        for (int mf = 0; mf < 4; mf++)
#pragma unroll
            for (int nf = 0; nf < 2; nf++)
#pragma unroll
                for (int q = 0; q < 4; q++) C[mf][nf][q] = 0.0f;

#pragma unroll
        for (int ks = 0; ks < 8; ks++) {
#pragma unroll
            for (int mf = 0; mf < 4; mf++) {
                unsigned int a[4];
                const unsigned int addr = smem_u32(
                    sA + ((mf * 16 + lrow) * AST + ks * 16 + lcol8) * 2);
                asm volatile(
                    "ldmatrix.sync.aligned.m8n8.x4.shared.b16 {%0,%1,%2,%3}, [%4];"
                    : "=r"(a[0]), "=r"(a[1]), "=r"(a[2]), "=r"(a[3])
                    : "r"(addr));
#pragma unroll
                for (int nf = 0; nf < 2; nf++)
                    asm volatile(
                        "mma.sync.aligned.m16n8k16.row.col.f32.f16.f16.f32 "
                        "{%0,%1,%2,%3}, {%4,%5,%6,%7}, {%8,%9}, {%0,%1,%2,%3};"
                        : "+f"(C[mf][nf][0]), "+f"(C[mf][nf][1]),
                          "+f"(C[mf][nf][2]), "+f"(C[mf][nf][3])
                        : "r"(a[0]), "r"(a[1]), "r"(a[2]), "r"(a[3]),
                          "r"(Bf[nf][ks][0]), "r"(Bf[nf][ks][1]));
            }
        }

        // STS tile it+1 into the other buffer (consumed in it-1; sync'd)
        sts_tile(buf ^ 1);
        // Prefetch tile it+2 into regs (DRAM latency hides under epilogue)
        ldg_tile(blockIdx.x + (it + 2) * gridDim.x);

        // ---- Epilogue -> TRANSPOSED srr[pcol][row] (conflict-free writes) ----
#pragma unroll
        for (int nf = 0; nf < 2; nf++) {
            const int pcol = w * 8 + nf * 4 + lc;
            const float bi = sbi[pcol], bj = sbj[pcol];
#pragma unroll
            for (int mf = 0; mf < 4; mf++) {
                const int r0 = mf * 16 + lr;
#pragma unroll
                for (int rp = 0; rp < 2; rp++) {
                    const float P = C[mf][nf][rp * 2] + bi;
                    const float J = C[mf][nf][rp * 2 + 1] + bj;
                    srr[pcol * 68 + (r0 + rp * 8)] =
                        sigmoid_unit(tanh_fast(P)) * fmaxf(J, 0.0f);
                }
            }
        }
        __syncthreads();   // all cols visible to all warps (cross-warp reduce)

        // ---- Sorted-segment reduce: thread (c = tid&63, strip = tid>>6) ----
        // Transposed srr -> contiguous 16-float run per thread: 4x LDS.128.
        {
            const int c = tid & 63;
            const int n0 = (tid >> 6) * 16;
            const float* run = srr + c * 68 + n0;
            const float4 v0 = *(const float4*)(run);
            const float4 v1 = *(const float4*)(run + 4);
            const float4 v2 = *(const float4*)(run + 8);
            const float4 v3 = *(const float4*)(run + 12);
            const int s0 = mseg[n0];
            if (s0 == mseg[n0 + 15]) {
                // uniform strip (common case): straight sum, one atomic
                if (s0 >= 0) {
                    float s = ((v0.x + v0.y) + (v0.z + v0.w))
                            + ((v1.x + v1.y) + (v1.z + v1.w))
                            + ((v2.x + v2.y) + (v2.z + v2.w))
                            + ((v3.x + v3.y) + (v3.z + v3.w));
                    atomicAdd(&g_pooled[s0 * DD + c], s);
                }
            } else {
                float vv[16] = {v0.x, v0.y, v0.z, v0.w, v1.x, v1.y, v1.z, v1.w,
                                v2.x, v2.y, v2.z, v2.w, v3.x, v3.y, v3.z, v3.w};
                float acc = 0.0f;
                int cur = s0;
#pragma unroll 4
                for (int n = 0; n < 16; n++) {
                    const int s = mseg[n0 + n];
                    if (s != cur) {
                        if (cur >= 0) atomicAdd(&g_pooled[cur * DD + c], acc);
                        acc = 0.0f;
                        cur = s;
                    }
                    acc += vv[n];
                }
                if (cur >= 0) atomicAdd(&g_pooled[cur * DD + c], acc);
            }
        }

        // Stage next tile's segment ids into the other sseg buffer
        stage_seg(blockIdx.x + (it + 1) * gridDim.x, buf ^ 1);

        __syncthreads();   // A buf^1 + sseg buf^1 visible; srr free for next tile
    }
}

// Per-graph readout: BN(inference) -> Dense(64->256)+ReLU -> Dense(256->1)
__global__ void readout_kernel(
    const float* __restrict__ gamma, const float* __restrict__ beta,
    const float* __restrict__ mov_mean, const float* __restrict__ mov_var,
    const float* __restrict__ W_h1, const float* __restrict__ b_h1,
    const float* __restrict__ W_out, const float* __restrict__ b_out,
    float* __restrict__ out)
{
    __shared__ float bn[DD];
    __shared__ float warp_part[8];
    const int g = blockIdx.x;
    const int t = threadIdx.x;

    if (t < DD) {
        const float p = g_pooled[g * DD + t];
        bn[t] = (p - mov_mean[t]) * rsqrtf(mov_var[t] + BN_EPS) * gamma[t] + beta[t];
    }
    __syncthreads();

    float y = 0.0f;
#pragma unroll 8
    for (int d = 0; d < DD; d++)
        y = fmaf(bn[d], W_h1[d * HH + t], y);
    y = fmaxf(y + b_h1[t], 0.0f);

    float v = y * W_out[t];
#pragma unroll
    for (int o = 16; o > 0; o >>= 1) v += __shfl_xor_sync(0xffffffffu, v, o);
    if ((t & 31) == 0) warp_part[t >> 5] = v;
    __syncthreads();
    if (t < 32) {
        float s = (t < 8) ? warp_part[t] : 0.0f;
#pragma unroll
        for (int o = 4; o > 0; o >>= 1) s += __shfl_xor_sync(0xffffffffu, s, o);
        if (t == 0) out[g] = s + b_out[0];
    }
}

extern "C" void kernel_launch(void* const* d_in, const int* in_sizes, int n_in,
                              void* d_out, int out_size)
{
    const float* x        = (const float*)d_in[0];
    const float* h        = (const float*)d_in[1];
    const float* W_i      = (const float*)d_in[2];
    const float* b_i      = (const float*)d_in[3];
    const float* W_j      = (const float*)d_in[4];
    const float* b_j      = (const float*)d_in[5];
    const float* gamma    = (const float*)d_in[6];
    const float* beta     = (const float*)d_in[7];
    const float* mov_mean = (const float*)d_in[8];
    const float* mov_var  = (const float*)d_in[9];
    const float* W_h1     = (const float*)d_in[10];
    const float* b_h1     = (const float*)d_in[11];
    const float* W_out    = (const float*)d_in[12];
    const float* b_out    = (const float*)d_in[13];
    const int*   seg      = (const int*)d_in[14];

    const int N = in_sizes[14];
    const int G = out_size;
    const int ntiles = (N + NT - 1) / NT;

    zero_pooled_kernel<<<256, 256>>>(G * DD);

    cudaFuncSetAttribute(node_mma_kernel, cudaFuncAttributeMaxDynamicSharedMemorySize,
                         SM_TOTAL);
    int grid = 296;
    if (grid > ntiles) grid = ntiles;
    node_mma_kernel<<<grid, 256, SM_TOTAL>>>(x, h, W_i, b_i, W_j, b_j, seg, N, ntiles);

    readout_kernel<<<G, 256>>>(gamma, beta, mov_mean, mov_var, W_h1, b_h1, W_out, b_out,
                               (float*)d_out);
}

// round 11
// speedup vs baseline: 2.1177x; 1.0292x over previous
#include <cuda_runtime.h>
#include <cuda_fp16.h>

#define DD 64
#define HH 256
#define MAXG 4096
#define BN_EPS 1e-3f
#define NT 64            // nodes per tile (GEMM M)
#define AST 136          // A smem row stride in halves (128 + 8 pad -> 272B)

__device__ float g_pooled[MAXG * DD];

// ---------- shared memory byte map (dynamic) ----------
#define SM_A0   0            // A buf 0: 64 x 136 fp16 = 17408 B
#define SM_A1   17408        // A buf 1
#define SM_RR   34816        // RR staging TRANSPOSED [col][node]: 64 x 68 fp32 = 17408 B
#define SM_BI   52224        // b_i (64 f)
#define SM_BJ   52480        // b_j (64 f)
#define SM_SEG  52736        // 2 x 64 ints (double-buffered)
#define SM_TOTAL 53248

__device__ __forceinline__ float tanh_fast(float v) {
    float r;
    asm("tanh.approx.f32 %0, %1;" : "=f"(r) : "f"(v));
    return r;
}
// sigmoid(t) for t in [-1,1]: odd Taylor poly, |err| < 3e-5 (no second MUFU)
__device__ __forceinline__ float sigmoid_unit(float t) {
    const float t2 = t * t;
    float p = fmaf(t2, -2.108134920634921e-4f, 2.0833333333e-3f);
    p = fmaf(t2, p, -2.0833333333e-2f);
    p = fmaf(t2, p, 0.25f);
    return fmaf(t, p, 0.5f);
}
__device__ __forceinline__ unsigned int smem_u32(const void* p) {
    unsigned int a;
    asm("{ .reg .u64 t; cvta.to.shared.u64 t, %1; cvt.u32.u64 %0, t; }" : "=r"(a) : "l"(p));
    return a;
}
__device__ __forceinline__ void mma16816(float* c, const unsigned int* a,
                                         const unsigned int* b) {
    asm volatile(
        "mma.sync.aligned.m16n8k16.row.col.f32.f16.f16.f32 "
        "{%0,%1,%2,%3}, {%4,%5,%6,%7}, {%8,%9}, {%0,%1,%2,%3};"
        : "+f"(c[0]), "+f"(c[1]), "+f"(c[2]), "+f"(c[3])
        : "r"(a[0]), "r"(a[1]), "r"(a[2]), "r"(a[3]), "r"(b[0]), "r"(b[1]));
}

__global__ void zero_pooled_kernel(int n) {
    for (int i = blockIdx.x * blockDim.x + threadIdx.x; i < n; i += gridDim.x * blockDim.x)
        g_pooled[i] = 0.0f;
}

extern __shared__ char smc[];

__global__ __launch_bounds__(256, 2) void node_mma_kernel(
    const float* __restrict__ x, const float* __restrict__ h,
    const float* __restrict__ W_i, const float* __restrict__ b_i,
    const float* __restrict__ W_j, const float* __restrict__ b_j,
    const int* __restrict__ seg, int N, int ntiles)
{
    const int tid  = threadIdx.x;
    const int w    = tid >> 5, lane = tid & 31;   // warp w owns cols [8w, 8w+8)
    const int lr   = lane >> 2;       // groupID 0..7
    const int lc   = lane & 3;        // 0..3

    float* srr = (float*)(smc + SM_RR);     // [col][node], stride 68
    float* sbi = (float*)(smc + SM_BI);
    float* sbj = (float*)(smc + SM_BJ);
    int*  sseg = (int*)(smc + SM_SEG);   // [2][64]

    if (tid < 64) {
        sbi[tid] = b_i[tid];
        sbj[tid] = b_j[tid];
    }

    // ---- Weight-stationary B fragments (fp16), split P / J GEMMs ----
    // P: col pcol = w*8 + lr from W_i, k = 0..127  (8 k-steps)
    // J: same col from W_j, k = 0..63              (4 k-steps, shares A frags)
    const int pcol = w * 8 + lr;
    unsigned int BfP[8][2], BfJ[4][2];
#pragma unroll
    for (int ks = 0; ks < 8; ks++) {
#pragma unroll
        for (int i = 0; i < 2; i++) {
            const int k0 = ks * 16 + lc * 2 + i * 8;
            __half2 hv = __floats2half2_rn(W_i[k0 * 64 + pcol],
                                           W_i[(k0 + 1) * 64 + pcol]);
            BfP[ks][i] = *(unsigned int*)&hv;
        }
    }
#pragma unroll
    for (int ks = 0; ks < 4; ks++) {
#pragma unroll
        for (int i = 0; i < 2; i++) {
            const int k0 = ks * 16 + lc * 2 + i * 8;
            __half2 hv = __floats2half2_rn(W_j[k0 * 64 + pcol],
                                           W_j[(k0 + 1) * 64 + pcol]);
            BfJ[ks][i] = *(unsigned int*)&hv;
        }
    }

    // ---- register-staged tile loaders (convert to half2 at load time) ----
    uint2 stc[8];
    auto ldg_tile = [&](int tile) {
        const int base = tile * NT;
#pragma unroll
        for (int j = 0; j < 8; j++) {
            const int idx = tid + j * 256;          // 2048 float4 slots
            const int n = idx >> 5, kc = (idx & 31) << 2;
            const int gn = base + n;
            float4 v = make_float4(0.f, 0.f, 0.f, 0.f);
            if (tile < ntiles && gn < N) {
                const float* src = (kc < 64) ? (h + (size_t)gn * 64 + kc)
                                             : (x + (size_t)gn * 64 + (kc - 64));
                v = *(const float4*)src;
            }
            __half2 lo = __floats2half2_rn(v.x, v.y);
            __half2 hi = __floats2half2_rn(v.z, v.w);
            stc[j].x = *(unsigned int*)&lo;
            stc[j].y = *(unsigned int*)&hi;
        }
    };
    auto sts_tile = [&](int buf) {
        char* ab = smc + (buf ? SM_A1 : SM_A0);
#pragma unroll
        for (int j = 0; j < 8; j++) {
            const int idx = tid + j * 256;
            const int n = idx >> 5, kc = (idx & 31) << 2;
            *(uint2*)(ab + (n * AST + kc) * 2) = stc[j];
        }
    };
    auto stage_seg = [&](int tile, int buf) {
        if (tid < NT) {
            const int gn = tile * NT + tid;
            sseg[buf * 64 + tid] = (gn < N && tile < ntiles) ? seg[gn] : -1;
        }
    };

    // Prologue: tile0 -> buf0 (+seg); tile1 -> regs
    ldg_tile(blockIdx.x);
    sts_tile(0);
    stage_seg(blockIdx.x, 0);
    ldg_tile(blockIdx.x + gridDim.x);
    __syncthreads();   // covers sbi/sbj + buf0 + seg0

    const int lrow = lane & 15;                // ldmatrix row within 16
    const int lcol8 = (lane >> 4) << 3;        // ldmatrix col-half offset

    for (int it = 0;; it++) {
        const int tile = blockIdx.x + it * gridDim.x;
        if (tile >= ntiles) break;
        const int buf = it & 1;
        const char* sA = smc + (buf ? SM_A1 : SM_A0);
        const int* mseg = sseg + buf * 64;

        // ---- Split GEMM: P (k=128) + J (k=64), shared A fragments ----
        float CP[4][4], CJ[4][4];
#pragma unroll
        for (int mf = 0; mf < 4; mf++)
#pragma unroll
            for (int q = 0; q < 4; q++) { CP[mf][q] = 0.0f; CJ[mf][q] = 0.0f; }

#pragma unroll
        for (int ks = 0; ks < 8; ks++) {
#pragma unroll
            for (int mf = 0; mf < 4; mf++) {
                unsigned int a[4];
                const unsigned int addr = smem_u32(
                    sA + ((mf * 16 + lrow) * AST + ks * 16 + lcol8) * 2);
                asm volatile(
                    "ldmatrix.sync.aligned.m8n8.x4.shared.b16 {%0,%1,%2,%3}, [%4];"
                    : "=r"(a[0]), "=r"(a[1]), "=r"(a[2]), "=r"(a[3])
                    : "r"(addr));
                mma16816(CP[mf], a, BfP[ks]);
                if (ks < 4) mma16816(CJ[mf], a, BfJ[ks]);
            }
        }

        // STS tile it+1 into the other buffer (consumed in it-1; sync'd)
        sts_tile(buf ^ 1);
        // Prefetch tile it+2 into regs (DRAM latency hides under epilogue)
        ldg_tile(blockIdx.x + (it + 2) * gridDim.x);

        // ---- Epilogue -> TRANSPOSED srr[col][row] (conflict-free writes) ----
        // CP[mf][q]: col = w*8 + 2*lc + (q&1), row = mf*16 + lr + (q>>1)*8
        {
            const int c0 = w * 8 + 2 * lc;
            const float bi0 = sbi[c0], bi1 = sbi[c0 + 1];
            const float bj0 = sbj[c0], bj1 = sbj[c0 + 1];
#pragma unroll
            for (int mf = 0; mf < 4; mf++) {
                const int r0 = mf * 16 + lr;
#pragma unroll
                for (int rp = 0; rp < 2; rp++) {
                    const int row = r0 + rp * 8;
                    const float P0 = CP[mf][rp * 2] + bi0;
                    const float P1 = CP[mf][rp * 2 + 1] + bi1;
                    const float J0 = CJ[mf][rp * 2] + bj0;
                    const float J1 = CJ[mf][rp * 2 + 1] + bj1;
                    srr[c0 * 68 + row] =
                        sigmoid_unit(tanh_fast(P0)) * fmaxf(J0, 0.0f);
                    srr[(c0 + 1) * 68 + row] =
                        sigmoid_unit(tanh_fast(P1)) * fmaxf(J1, 0.0f);
                }
            }
        }
        __syncthreads();   // all cols visible to all warps (cross-warp reduce)

        // ---- Sorted-segment reduce: thread (c = tid&63, strip = tid>>6) ----
        {
            const int c = tid & 63;
            const int n0 = (tid >> 6) * 16;
            const float* run = srr + c * 68 + n0;
            const float4 v0 = *(const float4*)(run);
            const float4 v1 = *(const float4*)(run + 4);
            const float4 v2 = *(const float4*)(run + 8);
            const float4 v3 = *(const float4*)(run + 12);
            const int s0 = mseg[n0];
            if (s0 == mseg[n0 + 15]) {
                if (s0 >= 0) {
                    float s = ((v0.x + v0.y) + (v0.z + v0.w))
                            + ((v1.x + v1.y) + (v1.z + v1.w))
                            + ((v2.x + v2.y) + (v2.z + v2.w))
                            + ((v3.x + v3.y) + (v3.z + v3.w));
                    atomicAdd(&g_pooled[s0 * DD + c], s);
                }
            } else {
                float vv[16] = {v0.x, v0.y, v0.z, v0.w, v1.x, v1.y, v1.z, v1.w,
                                v2.x, v2.y, v2.z, v2.w, v3.x, v3.y, v3.z, v3.w};
                float acc = 0.0f;
                int cur = s0;
#pragma unroll 4
                for (int n = 0; n < 16; n++) {
                    const int s = mseg[n0 + n];
                    if (s != cur) {
                        if (cur >= 0) atomicAdd(&g_pooled[cur * DD + c], acc);
                        acc = 0.0f;
                        cur = s;
                    }
                    acc += vv[n];
                }
                if (cur >= 0) atomicAdd(&g_pooled[cur * DD + c], acc);
            }
        }

        // Stage next tile's segment ids into the other sseg buffer
        stage_seg(blockIdx.x + (it + 1) * gridDim.x, buf ^ 1);

        __syncthreads();   // A buf^1 + sseg buf^1 visible; srr free for next tile
    }
}

// Per-graph readout: BN(inference) -> Dense(64->256)+ReLU -> Dense(256->1)
__global__ void readout_kernel(
    const float* __restrict__ gamma, const float* __restrict__ beta,
    const float* __restrict__ mov_mean, const float* __restrict__ mov_var,
    const float* __restrict__ W_h1, const float* __restrict__ b_h1,
    const float* __restrict__ W_out, const float* __restrict__ b_out,
    float* __restrict__ out)
{
    __shared__ float bn[DD];
    __shared__ float warp_part[8];
    const int g = blockIdx.x;
    const int t = threadIdx.x;

    if (t < DD) {
        const float p = g_pooled[g * DD + t];
        bn[t] = (p - mov_mean[t]) * rsqrtf(mov_var[t] + BN_EPS) * gamma[t] + beta[t];
    }
    __syncthreads();

    float y = 0.0f;
#pragma unroll 8
    for (int d = 0; d < DD; d++)
        y = fmaf(bn[d], W_h1[d * HH + t], y);
    y = fmaxf(y + b_h1[t], 0.0f);

    float v = y * W_out[t];
#pragma unroll
    for (int o = 16; o > 0; o >>= 1) v += __shfl_xor_sync(0xffffffffu, v, o);
    if ((t & 31) == 0) warp_part[t >> 5] = v;
    __syncthreads();
    if (t < 32) {
        float s = (t < 8) ? warp_part[t] : 0.0f;
#pragma unroll
        for (int o = 4; o > 0; o >>= 1) s += __shfl_xor_sync(0xffffffffu, s, o);
        if (t == 0) out[g] = s + b_out[0];
    }
}

extern "C" void kernel_launch(void* const* d_in, const int* in_sizes, int n_in,
                              void* d_out, int out_size)
{
    const float* x        = (const float*)d_in[0];
    const float* h        = (const float*)d_in[1];
    const float* W_i      = (const float*)d_in[2];
    const float* b_i      = (const float*)d_in[3];
    const float* W_j      = (const float*)d_in[4];
    const float* b_j      = (const float*)d_in[5];
    const float* gamma    = (const float*)d_in[6];
    const float* beta     = (const float*)d_in[7];
    const float* mov_mean = (const float*)d_in[8];
    const float* mov_var  = (const float*)d_in[9];
    const float* W_h1     = (const float*)d_in[10];
    const float* b_h1     = (const float*)d_in[11];
    const float* W_out    = (const float*)d_in[12];
    const float* b_out    = (const float*)d_in[13];
    const int*   seg      = (const int*)d_in[14];

    const int N = in_sizes[14];
    const int G = out_size;
    const int ntiles = (N + NT - 1) / NT;

    zero_pooled_kernel<<<256, 256>>>(G * DD);

    cudaFuncSetAttribute(node_mma_kernel, cudaFuncAttributeMaxDynamicSharedMemorySize,
                         SM_TOTAL);
    int grid = 296;
    if (grid > ntiles) grid = ntiles;
    node_mma_kernel<<<grid, 256, SM_TOTAL>>>(x, h, W_i, b_i, W_j, b_j, seg, N, ntiles);

    readout_kernel<<<G, 256>>>(gamma, beta, mov_mean, mov_var, W_h1, b_h1, W_out, b_out,
                               (float*)d_out);
}

// round 13
// speedup vs baseline: 2.1301x; 1.0058x over previous
#include <cuda_runtime.h>
#include <cuda_fp16.h>

#define DD 64
#define HH 256
#define MAXG 4096
#define BN_EPS 1e-3f
#define NT 64            // nodes per tile (GEMM M)
#define AST 136          // A smem row stride in halves (128 + 8 pad -> 272B)

__device__ float g_pooled[MAXG * DD];

// ---------- shared memory byte map (dynamic) ----------
#define SM_A0   0            // A buf 0: 64 x 136 fp16 = 17408 B
#define SM_A1   17408        // A buf 1
#define SM_RR0  34816        // srr buf 0 (TRANSPOSED [col][node]): 64 x 68 fp32
#define SM_RR1  52224        // srr buf 1
#define SM_BI   69632        // b_i (64 f)
#define SM_BJ   69888        // b_j (64 f)
#define SM_SEG  70144        // 4 x 64 ints (ring, slot = it & 3)
#define SM_TOTAL 71168

__device__ __forceinline__ float tanh_fast(float v) {
    float r;
    asm("tanh.approx.f32 %0, %1;" : "=f"(r) : "f"(v));
    return r;
}
// sigmoid(t) for t in [-1,1]: odd Taylor poly, |err| < 3e-5 (no second MUFU)
__device__ __forceinline__ float sigmoid_unit(float t) {
    const float t2 = t * t;
    float p = fmaf(t2, -2.108134920634921e-4f, 2.0833333333e-3f);
    p = fmaf(t2, p, -2.0833333333e-2f);
    p = fmaf(t2, p, 0.25f);
    return fmaf(t, p, 0.5f);
}
__device__ __forceinline__ unsigned int smem_u32(const void* p) {
    unsigned int a;
    asm("{ .reg .u64 t; cvta.to.shared.u64 t, %1; cvt.u32.u64 %0, t; }" : "=r"(a) : "l"(p));
    return a;
}
__device__ __forceinline__ void mma16816(float* c, const unsigned int* a,
                                         const unsigned int* b) {
    asm volatile(
        "mma.sync.aligned.m16n8k16.row.col.f32.f16.f16.f32 "
        "{%0,%1,%2,%3}, {%4,%5,%6,%7}, {%8,%9}, {%0,%1,%2,%3};"
        : "+f"(c[0]), "+f"(c[1]), "+f"(c[2]), "+f"(c[3])
        : "r"(a[0]), "r"(a[1]), "r"(a[2]), "r"(a[3]), "r"(b[0]), "r"(b[1]));
}

__global__ void zero_pooled_kernel(int n) {
    for (int i = blockIdx.x * blockDim.x + threadIdx.x; i < n; i += gridDim.x * blockDim.x)
        g_pooled[i] = 0.0f;
}

extern __shared__ char smc[];

__global__ __launch_bounds__(256, 2) void node_mma_kernel(
    const float* __restrict__ x, const float* __restrict__ h,
    const float* __restrict__ W_i, const float* __restrict__ b_i,
    const float* __restrict__ W_j, const float* __restrict__ b_j,
    const int* __restrict__ seg, int N, int ntiles)
{
    const int tid  = threadIdx.x;
    const int w    = tid >> 5, lane = tid & 31;   // warp w owns cols [8w, 8w+8)
    const int lr   = lane >> 2;       // groupID 0..7
    const int lc   = lane & 3;        // 0..3

    float* sbi = (float*)(smc + SM_BI);
    float* sbj = (float*)(smc + SM_BJ);
    int*  sseg = (int*)(smc + SM_SEG);   // [4][64] ring

    if (tid < 64) {
        sbi[tid] = b_i[tid];
        sbj[tid] = b_j[tid];
    }

    // ---- Weight-stationary B fragments (fp16), split P / J GEMMs ----
    const int pcol = w * 8 + lr;
    unsigned int BfP[8][2], BfJ[4][2];
#pragma unroll
    for (int ks = 0; ks < 8; ks++) {
#pragma unroll
        for (int i = 0; i < 2; i++) {
            const int k0 = ks * 16 + lc * 2 + i * 8;
            __half2 hv = __floats2half2_rn(W_i[k0 * 64 + pcol],
                                           W_i[(k0 + 1) * 64 + pcol]);
            BfP[ks][i] = *(unsigned int*)&hv;
        }
    }
#pragma unroll
    for (int ks = 0; ks < 4; ks++) {
#pragma unroll
        for (int i = 0; i < 2; i++) {
            const int k0 = ks * 16 + lc * 2 + i * 8;
            __half2 hv = __floats2half2_rn(W_j[k0 * 64 + pcol],
                                           W_j[(k0 + 1) * 64 + pcol]);
            BfJ[ks][i] = *(unsigned int*)&hv;
        }
    }

    // ---- register-staged tile loaders (convert to half2 at load time) ----
    uint2 stc[8];
    auto ldg_tile = [&](int it) {
        const int tile = (int)blockIdx.x + it * (int)gridDim.x;
        const int base = tile * NT;
#pragma unroll
        for (int j = 0; j < 8; j++) {
            const int idx = tid + j * 256;          // 2048 float4 slots
            const int n = idx >> 5, kc = (idx & 31) << 2;
            const int gn = base + n;
            float4 v = make_float4(0.f, 0.f, 0.f, 0.f);
            if (tile < ntiles && gn < N) {
                const float* src = (kc < 64) ? (h + (size_t)gn * 64 + kc)
                                             : (x + (size_t)gn * 64 + (kc - 64));
                v = *(const float4*)src;
            }
            __half2 lo = __floats2half2_rn(v.x, v.y);
            __half2 hi = __floats2half2_rn(v.z, v.w);
            stc[j].x = *(unsigned int*)&lo;
            stc[j].y = *(unsigned int*)&hi;
        }
    };
    auto sts_tile = [&](int it) {
        char* ab = smc + ((it & 1) ? SM_A1 : SM_A0);
#pragma unroll
        for (int j = 0; j < 8; j++) {
            const int idx = tid + j * 256;
            const int n = idx >> 5, kc = (idx & 31) << 2;
            *(uint2*)(ab + (n * AST + kc) * 2) = stc[j];
        }
    };
    auto stage_seg = [&](int it) {
        if (tid < NT) {
            const int tile = (int)blockIdx.x + it * (int)gridDim.x;
            const int gn = tile * NT + tid;
            sseg[(it & 3) * 64 + tid] = (gn < N && tile < ntiles) ? seg[gn] : -1;
        }
    };

    const int myTiles = (ntiles - 1 - (int)blockIdx.x) / (int)gridDim.x + 1;

    // Prologue: tile it=0 -> A buf0; it=1 -> regs; seg slots 0,1
    ldg_tile(0);
    sts_tile(0);
    stage_seg(0);
    stage_seg(1);
    ldg_tile(1);
    __syncthreads();   // biases + A buf0 + seg slots visible

    const int lrow = lane & 15;                // ldmatrix row within 16
    const int lcol8 = (lane >> 4) << 3;        // ldmatrix col-half offset

    // Loop runs one extra (drain) iteration to reduce the final tile.
    for (int it = 0; it <= myTiles; it++) {
        const bool work = (it < myTiles);

        if (work) {
            const char* sA = smc + ((it & 1) ? SM_A1 : SM_A0);

            // ---- Split GEMM: P (k=128) + J (k=64), shared A fragments ----
            float CP[4][4], CJ[4][4];
#pragma unroll
            for (int mf = 0; mf < 4; mf++)
#pragma unroll
                for (int q = 0; q < 4; q++) { CP[mf][q] = 0.0f; CJ[mf][q] = 0.0f; }

#pragma unroll
            for (int ks = 0; ks < 8; ks++) {
#pragma unroll
                for (int mf = 0; mf < 4; mf++) {
                    unsigned int a[4];
                    const unsigned int addr = smem_u32(
                        sA + ((mf * 16 + lrow) * AST + ks * 16 + lcol8) * 2);
                    asm volatile(
                        "ldmatrix.sync.aligned.m8n8.x4.shared.b16 {%0,%1,%2,%3}, [%4];"
                        : "=r"(a[0]), "=r"(a[1]), "=r"(a[2]), "=r"(a[3])
                        : "r"(addr));
                    mma16816(CP[mf], a, BfP[ks]);
                    if (ks < 4) mma16816(CJ[mf], a, BfJ[ks]);
                }
            }

            // STS tile it+1 into other A buffer; prefetch it+2 into regs
            sts_tile(it + 1);
            ldg_tile(it + 2);

            // ---- Epilogue -> TRANSPOSED srr[it&1][col][row] ----
            float* srr = (float*)(smc + ((it & 1) ? SM_RR1 : SM_RR0));
            const int c0 = w * 8 + 2 * lc;
            const float bi0 = sbi[c0], bi1 = sbi[c0 + 1];
            const float bj0 = sbj[c0], bj1 = sbj[c0 + 1];
#pragma unroll
            for (int mf = 0; mf < 4; mf++) {
                const int r0 = mf * 16 + lr;
#pragma unroll
                for (int rp = 0; rp < 2; rp++) {
                    const int row = r0 + rp * 8;
                    const float P0 = CP[mf][rp * 2] + bi0;
                    const float P1 = CP[mf][rp * 2 + 1] + bi1;
                    const float J0 = CJ[mf][rp * 2] + bj0;
                    const float J1 = CJ[mf][rp * 2 + 1] + bj1;
                    srr[c0 * 68 + row] =
                        sigmoid_unit(tanh_fast(P0)) * fmaxf(J0, 0.0f);
                    srr[(c0 + 1) * 68 + row] =
                        sigmoid_unit(tanh_fast(P1)) * fmaxf(J1, 0.0f);
                }
            }
        }

        // ---- Deferred reduce of tile it-1 from srr[(it-1)&1] ----
        // (visibility established by the loop-end barrier of iteration it-1)
        if (it > 0) {
            const int pit = it - 1;
            const float* prr = (const float*)(smc + ((pit & 1) ? SM_RR1 : SM_RR0));
            const int* mseg = sseg + (pit & 3) * 64;
            const int c = tid & 63;
            const int n0 = (tid >> 6) * 16;
            const float* run = prr + c * 68 + n0;
            const float4 v0 = *(const float4*)(run);
            const float4 v1 = *(const float4*)(run + 4);
            const float4 v2 = *(const float4*)(run + 8);
            const float4 v3 = *(const float4*)(run + 12);
            const int s0 = mseg[n0];
            if (s0 == mseg[n0 + 15]) {
                if (s0 >= 0) {
                    float s = ((v0.x + v0.y) + (v0.z + v0.w))
                            + ((v1.x + v1.y) + (v1.z + v1.w))
                            + ((v2.x + v2.y) + (v2.z + v2.w))
                            + ((v3.x + v3.y) + (v3.z + v3.w));
                    atomicAdd(&g_pooled[s0 * DD + c], s);
                }
            } else {
                float vv[16] = {v0.x, v0.y, v0.z, v0.w, v1.x, v1.y, v1.z, v1.w,
                                v2.x, v2.y, v2.z, v2.w, v3.x, v3.y, v3.z, v3.w};
                float acc = 0.0f;
                int cur = s0;
#pragma unroll 4
                for (int n = 0; n < 16; n++) {
                    const int s = mseg[n0 + n];
                    if (s != cur) {
                        if (cur >= 0) atomicAdd(&g_pooled[cur * DD + c], acc);
                        acc = 0.0f;
                        cur = s;
                    }
                    acc += vv[n];
                }
                if (cur >= 0) atomicAdd(&g_pooled[cur * DD + c], acc);
            }
        }

        // Stage seg ids for tile it+2 into ring slot (it+2)&3
        if (work) stage_seg(it + 2);

        __syncthreads();   // publish: A buf (it+1), srr (it), seg (it+2)
    }
}

// Per-graph readout: BN(inference) -> Dense(64->256)+ReLU -> Dense(256->1)
__global__ void readout_kernel(
    const float* __restrict__ gamma, const float* __restrict__ beta,
    const float* __restrict__ mov_mean, const float* __restrict__ mov_var,
    const float* __restrict__ W_h1, const float* __restrict__ b_h1,
    const float* __restrict__ W_out, const float* __restrict__ b_out,
    float* __restrict__ out)
{
    __shared__ float bn[DD];
    __shared__ float warp_part[8];
    const int g = blockIdx.x;
    const int t = threadIdx.x;

    if (t < DD) {
        const float p = g_pooled[g * DD + t];
        bn[t] = (p - mov_mean[t]) * rsqrtf(mov_var[t] + BN_EPS) * gamma[t] + beta[t];
    }
    __syncthreads();

    float y = 0.0f;
#pragma unroll 8
    for (int d = 0; d < DD; d++)
        y = fmaf(bn[d], W_h1[d * HH + t], y);
    y = fmaxf(y + b_h1[t], 0.0f);

    float v = y * W_out[t];
#pragma unroll
    for (int o = 16; o > 0; o >>= 1) v += __shfl_xor_sync(0xffffffffu, v, o);
    if ((t & 31) == 0) warp_part[t >> 5] = v;
    __syncthreads();
    if (t < 32) {
        float s = (t < 8) ? warp_part[t] : 0.0f;
#pragma unroll
        for (int o = 4; o > 0; o >>= 1) s += __shfl_xor_sync(0xffffffffu, s, o);
        if (t == 0) out[g] = s + b_out[0];
    }
}

extern "C" void kernel_launch(void* const* d_in, const int* in_sizes, int n_in,
                              void* d_out, int out_size)
{
    const float* x        = (const float*)d_in[0];
    const float* h        = (const float*)d_in[1];
    const float* W_i      = (const float*)d_in[2];
    const float* b_i      = (const float*)d_in[3];
    const float* W_j      = (const float*)d_in[4];
    const float* b_j      = (const float*)d_in[5];
    const float* gamma    = (const float*)d_in[6];
    const float* beta     = (const float*)d_in[7];
    const float* mov_mean = (const float*)d_in[8];
    const float* mov_var  = (const float*)d_in[9];
    const float* W_h1     = (const float*)d_in[10];
    const float* b_h1     = (const float*)d_in[11];
    const float* W_out    = (const float*)d_in[12];
    const float* b_out    = (const float*)d_in[13];
    const int*   seg      = (const int*)d_in[14];

    const int N = in_sizes[14];
    const int G = out_size;
    const int ntiles = (N + NT - 1) / NT;

    zero_pooled_kernel<<<256, 256>>>(G * DD);

    cudaFuncSetAttribute(node_mma_kernel, cudaFuncAttributeMaxDynamicSharedMemorySize,
                         SM_TOTAL);
    int grid = 296;
    if (grid > ntiles) grid = ntiles;
    node_mma_kernel<<<grid, 256, SM_TOTAL>>>(x, h, W_i, b_i, W_j, b_j, seg, N, ntiles);

    readout_kernel<<<G, 256>>>(gamma, beta, mov_mean, mov_var, W_h1, b_h1, W_out, b_out,
                               (float*)d_out);
}